// round 2
// baseline (speedup 1.0000x reference)
#include <cuda_runtime.h>

#define NN 50000
#define NE 800000

// scratch (allocation-free: __device__ globals)
__device__ float g_sums[NN * 64];
__device__ float g_cnt[NN];

// ---------------------------------------------------------------------------
__global__ void zero_kernel() {
    int i = blockIdx.x * blockDim.x + threadIdx.x;
    if (i < NN * 64) g_sums[i] = 0.0f;
    if (i < NN) g_cnt[i] = 0.0f;
}

__global__ void count_kernel(const int* __restrict__ eidx) {
    int e = blockIdx.x * blockDim.x + threadIdx.x;
    if (e < NE) atomicAdd(&g_cnt[eidx[e]], 1.0f);
}

// ---------------------------------------------------------------------------
#define STEP4(aval, bvec, ACC)                \
    ACC[0] = fmaf(aval, bvec.x, ACC[0]);      \
    ACC[1] = fmaf(aval, bvec.y, ACC[1]);      \
    ACC[2] = fmaf(aval, bvec.z, ACC[2]);      \
    ACC[3] = fmaf(aval, bvec.w, ACC[3]);

#define STEP2(aval, bvec, ACC)                \
    ACC[0] = fmaf(aval, bvec.x, ACC[0]);      \
    ACC[1] = fmaf(aval, bvec.y, ACC[1]);

// Edge kernel: per 128-edge tile, msg = [src[col]|edge_attr] (E x 128),
// h1 = relu(msg @ W1a^T + b1a) (E x 128), h2 = h1 @ W1b^T + b1b (E x 64),
// atomic scatter-add into g_sums[row].
// smem floats: sW1aT 16384 | sW1bT 8192 | sb1a 128 | sb1b 64 | sX 16384 = 41152
__global__ __launch_bounds__(512, 1)
void edge_kernel(const float* __restrict__ src, const int* __restrict__ eidx,
                 const float* __restrict__ eattr,
                 const float* __restrict__ W1a, const float* __restrict__ b1a,
                 const float* __restrict__ W1b, const float* __restrict__ b1b)
{
    extern __shared__ float sm[];
    float* sW1aT = sm;             // [k][j]  (128x128)
    float* sW1bT = sm + 16384;     // [h][o]  (128x64)
    float* sb1a  = sm + 24576;
    float* sb1b  = sm + 24704;
    float* sX    = sm + 24768;     // [e][k]  (128x128), reused for h1 [e][j]

    const int tid = threadIdx.x;
    for (int idx = tid; idx < 16384; idx += 512) { int j = idx >> 7, k = idx & 127; sW1aT[k * 128 + j] = W1a[idx]; }
    for (int idx = tid; idx < 8192;  idx += 512) { int o = idx >> 7, h = idx & 127; sW1bT[h * 64 + o]  = W1b[idx]; }
    if (tid < 128) sb1a[tid] = b1a[tid];
    if (tid < 64)  sb1b[tid] = b1b[tid];

    const int* rowI = eidx;        // edge_index is INT32 (jax x64 disabled)
    const int* colI = eidx + NE;

    const int lane = tid & 31, warp = tid >> 5;
    const int e0 = warp * 8;    // 16 warps x 8 edges = 128
    const int j0 = lane * 4;    // 32 lanes x 4 = 128 hidden
    const int o0 = lane * 2;    // 32 lanes x 2 = 64 out

    const int ntiles = NE / 128;  // 6250 exact
    for (int t = blockIdx.x; t < ntiles; t += gridDim.x) {
        const int base = t * 128;
        __syncthreads();  // prior readers of sX done (also covers weight staging on iter 0)

        // ---- stage msg tile [128 e][128 k] (float4, fully coalesced) ----
        #pragma unroll
        for (int i = 0; i < 8; i++) {
            int idx4 = i * 512 + tid;          // 0..4095
            int e  = idx4 >> 5;                // 0..127
            int k4 = (idx4 & 31) * 4;          // 0..124
            int ge = base + e;
            float4 v;
            if (k4 < 64) {
                int c = colI[ge];
                v = *(const float4*)(src + (long long)c * 64 + k4);
            } else {
                v = *(const float4*)(eattr + (long long)ge * 64 + (k4 - 64));
            }
            *(float4*)(sX + e * 128 + k4) = v;
        }
        __syncthreads();

        // ---- GEMM1: acc[8 e][4 j] over k=128 ----
        float acc[8][4];
        #pragma unroll
        for (int ee = 0; ee < 8; ee++) { acc[ee][0] = 0.f; acc[ee][1] = 0.f; acc[ee][2] = 0.f; acc[ee][3] = 0.f; }

        #pragma unroll 1
        for (int k = 0; k < 128; k += 4) {
            const float4 b0 = *(const float4*)(sW1aT + (k    ) * 128 + j0);
            const float4 b1 = *(const float4*)(sW1aT + (k + 1) * 128 + j0);
            const float4 b2 = *(const float4*)(sW1aT + (k + 2) * 128 + j0);
            const float4 b3 = *(const float4*)(sW1aT + (k + 3) * 128 + j0);
            #pragma unroll
            for (int ee = 0; ee < 8; ee++) {
                const float4 a = *(const float4*)(sX + (e0 + ee) * 128 + k);  // warp-uniform: broadcast
                STEP4(a.x, b0, acc[ee]);
                STEP4(a.y, b1, acc[ee]);
                STEP4(a.z, b2, acc[ee]);
                STEP4(a.w, b3, acc[ee]);
            }
        }
        __syncthreads();  // everyone done reading msg from sX

        // ---- bias + relu, write h1 into sX[e][j] (float4, conflict-free) ----
        {
            const float4 bb = *(const float4*)(sb1a + j0);
            #pragma unroll
            for (int ee = 0; ee < 8; ee++) {
                float4 h;
                h.x = fmaxf(acc[ee][0] + bb.x, 0.f);
                h.y = fmaxf(acc[ee][1] + bb.y, 0.f);
                h.z = fmaxf(acc[ee][2] + bb.z, 0.f);
                h.w = fmaxf(acc[ee][3] + bb.w, 0.f);
                *(float4*)(sX + (e0 + ee) * 128 + j0) = h;
            }
        }
        __syncthreads();

        // ---- GEMM2: acc2[8 e][2 o] over h=128 ----
        float acc2[8][2];
        #pragma unroll
        for (int ee = 0; ee < 8; ee++) { acc2[ee][0] = 0.f; acc2[ee][1] = 0.f; }

        #pragma unroll 1
        for (int k = 0; k < 128; k += 4) {
            const float2 c0 = *(const float2*)(sW1bT + (k    ) * 64 + o0);
            const float2 c1 = *(const float2*)(sW1bT + (k + 1) * 64 + o0);
            const float2 c2 = *(const float2*)(sW1bT + (k + 2) * 64 + o0);
            const float2 c3 = *(const float2*)(sW1bT + (k + 3) * 64 + o0);
            #pragma unroll
            for (int ee = 0; ee < 8; ee++) {
                const float4 a = *(const float4*)(sX + (e0 + ee) * 128 + k);  // broadcast
                STEP2(a.x, c0, acc2[ee]);
                STEP2(a.y, c1, acc2[ee]);
                STEP2(a.z, c2, acc2[ee]);
                STEP2(a.w, c3, acc2[ee]);
            }
        }

        // ---- scatter-add (coalesced 256B RED per warp per edge) ----
        {
            const float2 bo = *(const float2*)(sb1b + o0);
            #pragma unroll
            for (int ee = 0; ee < 8; ee++) {
                int r = rowI[base + e0 + ee];   // warp-uniform load
                float* dst = g_sums + (long long)r * 64 + o0;
                atomicAdd(dst,     acc2[ee][0] + bo.x);
                atomicAdd(dst + 1, acc2[ee][1] + bo.y);
            }
        }
    }
}

// ---------------------------------------------------------------------------
// Node kernel: per 64-node tile,
//   A = [src | agg] (64x128), h = relu(A @ W2a^T + b2a) (64x128),
//   z = h @ W2b^T + b2b (64x64) written back into A[:,64:128] (over agg),
//   out = A @ WrPerm^T + br   where WrPerm has k-dim swapped halves so that
//   A=[src|z] matches concat(z,src) of the reference.
// smem floats: sW2aT 16384 | sW2bT 8192 | sWrT 8192 | sb2a 128 | sb2b 64 | sbr 64
//              | sA 8192 | sB 8192  = 49408
__global__ __launch_bounds__(512, 1)
void node_kernel(const float* __restrict__ src,
                 const float* __restrict__ W2a, const float* __restrict__ b2a,
                 const float* __restrict__ W2b, const float* __restrict__ b2b,
                 const float* __restrict__ Wr,  const float* __restrict__ br,
                 float* __restrict__ out)
{
    extern __shared__ float sm[];
    float* sW2aT = sm;               // [k][j] 128x128
    float* sW2bT = sm + 16384;       // [h][o] 128x64
    float* sWrT  = sm + 24576;       // [kperm][o] 128x64
    float* sb2a  = sm + 32768;
    float* sb2b  = sm + 32896;
    float* sbr   = sm + 32960;
    float* sA    = sm + 33024;       // [n][k] 64x128
    float* sB    = sm + 41216;       // [n][j] 64x128

    const int tid = threadIdx.x;
    for (int idx = tid; idx < 16384; idx += 512) { int j = idx >> 7, k = idx & 127; sW2aT[k * 128 + j] = W2a[idx]; }
    for (int idx = tid; idx < 8192;  idx += 512) { int o = idx >> 7, h = idx & 127; sW2bT[h * 64 + o]  = W2b[idx]; }
    for (int idx = tid; idx < 8192;  idx += 512) {
        int o = idx >> 7, k = idx & 127;
        int kp = (k < 64) ? (k + 64) : (k - 64);  // swap halves: A=[src|z] vs concat(z,src)
        sWrT[kp * 64 + o] = Wr[idx];
    }
    if (tid < 128) sb2a[tid] = b2a[tid];
    if (tid < 64)  sb2b[tid] = b2b[tid];
    if (tid < 64)  sbr[tid]  = br[tid];

    const int lane = tid & 31, warp = tid >> 5;
    const int n0 = warp * 4;    // 16 warps x 4 nodes = 64
    const int j0 = lane * 4;
    const int o0 = lane * 2;

    const int ntiles = (NN + 63) / 64;   // 782 (last partial)
    for (int t = blockIdx.x; t < ntiles; t += gridDim.x) {
        const int base = t * 64;
        __syncthreads();

        // ---- stage A = [src | sums/max(cnt,1)] ----
        #pragma unroll
        for (int i = 0; i < 4; i++) {
            int idx4 = i * 512 + tid;      // 0..2047
            int n  = idx4 >> 5;            // 0..63
            int k4 = (idx4 & 31) * 4;
            int gn = base + n;
            float4 v = make_float4(0.f, 0.f, 0.f, 0.f);
            if (gn < NN) {
                if (k4 < 64) {
                    v = *(const float4*)(src + (long long)gn * 64 + k4);
                } else {
                    float inv = 1.0f / fmaxf(g_cnt[gn], 1.0f);
                    float4 s = *(const float4*)(g_sums + (long long)gn * 64 + (k4 - 64));
                    v = make_float4(s.x * inv, s.y * inv, s.z * inv, s.w * inv);
                }
            }
            *(float4*)(sA + n * 128 + k4) = v;
        }
        __syncthreads();

        // ---- GEMM1: h = relu(A @ W2a^T + b2a) -> sB ----
        float acc[4][4];
        #pragma unroll
        for (int ii = 0; ii < 4; ii++) { acc[ii][0] = 0.f; acc[ii][1] = 0.f; acc[ii][2] = 0.f; acc[ii][3] = 0.f; }

        #pragma unroll 1
        for (int k = 0; k < 128; k += 4) {
            const float4 b0 = *(const float4*)(sW2aT + (k    ) * 128 + j0);
            const float4 b1 = *(const float4*)(sW2aT + (k + 1) * 128 + j0);
            const float4 b2 = *(const float4*)(sW2aT + (k + 2) * 128 + j0);
            const float4 b3 = *(const float4*)(sW2aT + (k + 3) * 128 + j0);
            #pragma unroll
            for (int ii = 0; ii < 4; ii++) {
                const float4 a = *(const float4*)(sA + (n0 + ii) * 128 + k);
                STEP4(a.x, b0, acc[ii]);
                STEP4(a.y, b1, acc[ii]);
                STEP4(a.z, b2, acc[ii]);
                STEP4(a.w, b3, acc[ii]);
            }
        }
        {
            const float4 bb = *(const float4*)(sb2a + j0);
            #pragma unroll
            for (int ii = 0; ii < 4; ii++) {
                float4 h;
                h.x = fmaxf(acc[ii][0] + bb.x, 0.f);
                h.y = fmaxf(acc[ii][1] + bb.y, 0.f);
                h.z = fmaxf(acc[ii][2] + bb.z, 0.f);
                h.w = fmaxf(acc[ii][3] + bb.w, 0.f);
                *(float4*)(sB + (n0 + ii) * 128 + j0) = h;
            }
        }
        __syncthreads();

        // ---- GEMM2: z = h @ W2b^T + b2b -> sA[:, 64:128] ----
        float acc2[4][2];
        #pragma unroll
        for (int ii = 0; ii < 4; ii++) { acc2[ii][0] = 0.f; acc2[ii][1] = 0.f; }

        #pragma unroll 1
        for (int k = 0; k < 128; k += 4) {
            const float2 c0 = *(const float2*)(sW2bT + (k    ) * 64 + o0);
            const float2 c1 = *(const float2*)(sW2bT + (k + 1) * 64 + o0);
            const float2 c2 = *(const float2*)(sW2bT + (k + 2) * 64 + o0);
            const float2 c3 = *(const float2*)(sW2bT + (k + 3) * 64 + o0);
            #pragma unroll
            for (int ii = 0; ii < 4; ii++) {
                const float4 a = *(const float4*)(sB + (n0 + ii) * 128 + k);
                STEP2(a.x, c0, acc2[ii]);
                STEP2(a.y, c1, acc2[ii]);
                STEP2(a.z, c2, acc2[ii]);
                STEP2(a.w, c3, acc2[ii]);
            }
        }
        {
            const float2 bz = *(const float2*)(sb2b + o0);
            #pragma unroll
            for (int ii = 0; ii < 4; ii++) {
                *(float2*)(sA + (n0 + ii) * 128 + 64 + o0) =
                    make_float2(acc2[ii][0] + bz.x, acc2[ii][1] + bz.y);
            }
        }
        __syncthreads();

        // ---- GEMM3: out = [src|z] @ WrPerm^T + br ----
        float acc3[4][2];
        #pragma unroll
        for (int ii = 0; ii < 4; ii++) { acc3[ii][0] = 0.f; acc3[ii][1] = 0.f; }

        #pragma unroll 1
        for (int k = 0; k < 128; k += 4) {
            const float2 c0 = *(const float2*)(sWrT + (k    ) * 64 + o0);
            const float2 c1 = *(const float2*)(sWrT + (k + 1) * 64 + o0);
            const float2 c2 = *(const float2*)(sWrT + (k + 2) * 64 + o0);
            const float2 c3 = *(const float2*)(sWrT + (k + 3) * 64 + o0);
            #pragma unroll
            for (int ii = 0; ii < 4; ii++) {
                const float4 a = *(const float4*)(sA + (n0 + ii) * 128 + k);
                STEP2(a.x, c0, acc3[ii]);
                STEP2(a.y, c1, acc3[ii]);
                STEP2(a.z, c2, acc3[ii]);
                STEP2(a.w, c3, acc3[ii]);
            }
        }
        {
            const float2 bo = *(const float2*)(sbr + o0);
            #pragma unroll
            for (int ii = 0; ii < 4; ii++) {
                int gn = base + n0 + ii;
                if (gn < NN) {
                    *(float2*)(out + (long long)gn * 64 + o0) =
                        make_float2(acc3[ii][0] + bo.x, acc3[ii][1] + bo.y);
                }
            }
        }
    }
}

// ---------------------------------------------------------------------------
extern "C" void kernel_launch(void* const* d_in, const int* in_sizes, int n_in,
                              void* d_out, int out_size) {
    const float* src   = (const float*)d_in[0];
    const int*   eidx  = (const int*)d_in[1];    // int32! (jax x64 disabled)
    const float* eattr = (const float*)d_in[2];
    // d_in[3] = u (unused), d_in[4] = batch (unused)
    const float* W1a = (const float*)d_in[5];
    const float* b1a = (const float*)d_in[6];
    const float* W1b = (const float*)d_in[7];
    const float* b1b = (const float*)d_in[8];
    const float* W2a = (const float*)d_in[9];
    const float* b2a = (const float*)d_in[10];
    const float* W2b = (const float*)d_in[11];
    const float* b2b = (const float*)d_in[12];
    const float* Wr  = (const float*)d_in[13];
    const float* br  = (const float*)d_in[14];
    float* out = (float*)d_out;

    const int smem_edge = 41152 * 4;   // 164608 B
    const int smem_node = 49408 * 4;   // 197632 B
    cudaFuncSetAttribute(edge_kernel, cudaFuncAttributeMaxDynamicSharedMemorySize, smem_edge);
    cudaFuncSetAttribute(node_kernel, cudaFuncAttributeMaxDynamicSharedMemorySize, smem_node);

    zero_kernel<<<(NN * 64 + 255) / 256, 256>>>();
    count_kernel<<<(NE + 255) / 256, 256>>>(eidx);
    edge_kernel<<<148, 512, smem_edge>>>(src, eidx, eattr, W1a, b1a, W1b, b1b);
    node_kernel<<<148, 512, smem_node>>>(src, W2a, b2a, W2b, b2b, Wr, br, out);
}

// round 4
// speedup vs baseline: 1.4159x; 1.4159x over previous
#include <cuda_runtime.h>
#include <cuda_bf16.h>
#include <cstdint>

#define NN 50000
#define NE 800000
#define XB 272   // bytes per bf16 row: 136 elements (128 + 8 pad) -> conflict-free frags

__device__ __align__(16) float g_sums[NN * 64];
__device__ float g_cnt[NN];

__global__ void zero_kernel() {
    int i = blockIdx.x * blockDim.x + threadIdx.x;
    if (i < NN * 64) g_sums[i] = 0.0f;
    if (i < NN) g_cnt[i] = 0.0f;
}

// fp32x2 -> bf16x2 hi + bf16x2 lo (residual)
__device__ __forceinline__ uint32_t pack_split(float2 v, uint32_t* lo32) {
    __nv_bfloat16 h0 = __float2bfloat16(v.x), h1 = __float2bfloat16(v.y);
    float r0 = v.x - __bfloat162float(h0), r1 = v.y - __bfloat162float(h1);
    __nv_bfloat16 l0 = __float2bfloat16(r0), l1 = __float2bfloat16(r1);
    *lo32 = (uint32_t)__bfloat16_as_ushort(l0) | ((uint32_t)__bfloat16_as_ushort(l1) << 16);
    return (uint32_t)__bfloat16_as_ushort(h0) | ((uint32_t)__bfloat16_as_ushort(h1) << 16);
}

__device__ __forceinline__ void mma_bf16(float d[4], const uint32_t a[4], const uint32_t b[2]) {
    asm volatile(
        "mma.sync.aligned.m16n8k16.row.col.f32.bf16.bf16.f32 "
        "{%0,%1,%2,%3}, {%4,%5,%6,%7}, {%8,%9}, {%0,%1,%2,%3};"
        : "+f"(d[0]), "+f"(d[1]), "+f"(d[2]), "+f"(d[3])
        : "r"(a[0]), "r"(a[1]), "r"(a[2]), "r"(a[3]), "r"(b[0]), "r"(b[1]));
}

// A fragment (row-major, 16x16): row includes lane>>2; kb includes k0*32 + (lane&3)*4
__device__ __forceinline__ void ldA(uint32_t a[4], const char* buf, int row, int kb) {
    const char* p = buf + row * XB + kb;
    a[0] = *(const uint32_t*)p;
    a[1] = *(const uint32_t*)(p + 8 * XB);
    a[2] = *(const uint32_t*)(p + 16);
    a[3] = *(const uint32_t*)(p + 8 * XB + 16);
}
// B fragment (col-major 16x8 == weight stored [n][k] row-major)
__device__ __forceinline__ void ldB(uint32_t b[2], const char* buf, int row, int kb) {
    const char* p = buf + row * XB + kb;
    b[0] = *(const uint32_t*)p;
    b[1] = *(const uint32_t*)(p + 16);
}

#define REDV2(ptr, x0, x1) \
    asm volatile("red.global.add.v2.f32 [%0], {%1,%2};" :: "l"(ptr), "f"(x0), "f"(x1) : "memory")

// stage fp32 weight [R][128] row-major -> bf16 hi/lo [R][136], optional k-half swap
__device__ __forceinline__ void stage_w(const float* __restrict__ W, char* hi, char* lo,
                                        int R, int swap) {
    for (int idx = threadIdx.x; idx < R * 64; idx += 512) {
        int r = idx >> 6, kp = idx & 63;
        float2 v = *(const float2*)(W + r * 128 + kp * 2);
        uint32_t l32, h32 = pack_split(v, &l32);
        int kd = swap ? (kp ^ 32) : kp;
        *(uint32_t*)(hi + r * XB + kd * 4) = h32;
        *(uint32_t*)(lo + r * XB + kd * 4) = l32;
    }
}

// ============================== EDGE KERNEL ==================================
// smem: b1a 512 | b1b 256 | col 512 -> 1280
// Xhi 34816 | Xlo 34816 | WaHi 34816 | WaLo 34816 | WbHi 17408 | WbLo 17408
#define EO_XHI  1280
#define EO_XLO  36096
#define EO_WAHI 70912
#define EO_WALO 105728
#define EO_WBHI 140544
#define EO_WBLO 157952
#define SMEM_EDGE 175360

__global__ __launch_bounds__(512, 1)
void edge_kernel(const float* __restrict__ src, const int* __restrict__ eidx,
                 const float* __restrict__ eattr,
                 const float* __restrict__ W1a, const float* __restrict__ b1a,
                 const float* __restrict__ W1b, const float* __restrict__ b1b)
{
    extern __shared__ char sm[];
    float* sb1a = (float*)sm;
    float* sb1b = (float*)(sm + 512);
    int*   sCol = (int*)(sm + 768);
    char* sXhi = sm + EO_XHI;  char* sXlo = sm + EO_XLO;
    char* sWaHi = sm + EO_WAHI; char* sWaLo = sm + EO_WALO;
    char* sWbHi = sm + EO_WBHI; char* sWbLo = sm + EO_WBLO;

    const int tid = threadIdx.x, lane = tid & 31, w = tid >> 5;
    stage_w(W1a, sWaHi, sWaLo, 128, 0);
    stage_w(W1b, sWbHi, sWbLo, 64, 0);
    if (tid < 128) sb1a[tid] = b1a[tid];
    if (tid < 64)  sb1b[tid] = b1b[tid];

    const int* rowI = eidx;        // int32 (jax x64 disabled)
    const int* colI = eidx + NE;
    const int p = w & 3, q = w >> 2;      // p: m-strip pair, q: n-group
    const int r4 = lane >> 2;             // fragment row within 8
    const int cb = (lane & 3) * 4;        // fragment k-byte offset
    const int c2 = (lane & 3) * 2;        // fragment col offset (elements)

    for (int t = blockIdx.x; t < NE / 128; t += gridDim.x) {
        const int base = t * 128;
        __syncthreads();
        if (tid < 128) sCol[tid] = colI[base + tid];
        __syncthreads();

        // ---- stage X = [src[col] | eattr] bf16 hi/lo ----
        #pragma unroll
        for (int i = 0; i < 16; i++) {
            int idx = i * 512 + tid;
            int e = idx >> 6, kp = idx & 63;
            const float* ptr = (kp < 32) ? src + (size_t)sCol[e] * 64 + kp * 2
                                         : eattr + (size_t)(base + e) * 64 + (kp - 32) * 2;
            float2 v = *(const float2*)ptr;
            uint32_t l32, h32 = pack_split(v, &l32);
            *(uint32_t*)(sXhi + e * XB + kp * 4) = h32;
            *(uint32_t*)(sXlo + e * XB + kp * 4) = l32;
        }
        __syncthreads();

        // ---- GEMM1: h = X @ W1a^T  (2 m-strips x 4 n8-tiles per warp) ----
        float acc[2][4][4];
        #pragma unroll
        for (int s = 0; s < 2; s++)
            #pragma unroll
            for (int j = 0; j < 4; j++)
                { acc[s][j][0]=0.f; acc[s][j][1]=0.f; acc[s][j][2]=0.f; acc[s][j][3]=0.f; }

        #pragma unroll
        for (int k0 = 0; k0 < 8; k0++) {
            int kb = k0 * 32 + cb;
            uint32_t ah[2][4], al[2][4];
            #pragma unroll
            for (int s = 0; s < 2; s++) {
                int row = p * 32 + s * 16 + r4;
                ldA(ah[s], sXhi, row, kb);
                ldA(al[s], sXlo, row, kb);
            }
            #pragma unroll
            for (int j = 0; j < 4; j++) {
                int n0 = q * 32 + j * 8 + r4;
                uint32_t bh[2], bl[2];
                ldB(bh, sWaHi, n0, kb);
                ldB(bl, sWaLo, n0, kb);
                #pragma unroll
                for (int s = 0; s < 2; s++) {
                    mma_bf16(acc[s][j], ah[s], bh);
                    mma_bf16(acc[s][j], al[s], bh);
                    mma_bf16(acc[s][j], ah[s], bl);
                }
            }
        }
        __syncthreads();   // all warps done reading X

        // ---- epi1: relu(+b1a) -> h (hi/lo) overwriting X buffers ----
        #pragma unroll
        for (int s = 0; s < 2; s++) {
            int r0 = p * 32 + s * 16 + r4;
            #pragma unroll
            for (int j = 0; j < 4; j++) {
                int c0 = q * 32 + j * 8 + c2;
                float bx = sb1a[c0], by = sb1a[c0 + 1];
                float2 v0 = make_float2(fmaxf(acc[s][j][0] + bx, 0.f), fmaxf(acc[s][j][1] + by, 0.f));
                float2 v1 = make_float2(fmaxf(acc[s][j][2] + bx, 0.f), fmaxf(acc[s][j][3] + by, 0.f));
                uint32_t l32, h32;
                h32 = pack_split(v0, &l32);
                *(uint32_t*)(sXhi + r0 * XB + c0 * 2) = h32;
                *(uint32_t*)(sXlo + r0 * XB + c0 * 2) = l32;
                h32 = pack_split(v1, &l32);
                *(uint32_t*)(sXhi + (r0 + 8) * XB + c0 * 2) = h32;
                *(uint32_t*)(sXlo + (r0 + 8) * XB + c0 * 2) = l32;
            }
        }
        __syncthreads();

        // ---- GEMM2: D2 = h @ W1b^T  (2 strips x 2 n8-tiles per warp) ----
        float acc2[2][2][4];
        #pragma unroll
        for (int s = 0; s < 2; s++)
            #pragma unroll
            for (int j = 0; j < 2; j++)
                { acc2[s][j][0]=0.f; acc2[s][j][1]=0.f; acc2[s][j][2]=0.f; acc2[s][j][3]=0.f; }

        #pragma unroll
        for (int k0 = 0; k0 < 8; k0++) {
            int kb = k0 * 32 + cb;
            uint32_t ah[2][4], al[2][4];
            #pragma unroll
            for (int s = 0; s < 2; s++) {
                int row = p * 32 + s * 16 + r4;
                ldA(ah[s], sXhi, row, kb);
                ldA(al[s], sXlo, row, kb);
            }
            #pragma unroll
            for (int j = 0; j < 2; j++) {
                int n0 = q * 16 + j * 8 + r4;
                uint32_t bh[2], bl[2];
                ldB(bh, sWbHi, n0, kb);
                ldB(bl, sWbLo, n0, kb);
                #pragma unroll
                for (int s = 0; s < 2; s++) {
                    mma_bf16(acc2[s][j], ah[s], bh);
                    mma_bf16(acc2[s][j], al[s], bh);
                    mma_bf16(acc2[s][j], ah[s], bl);
                }
            }
        }

        // ---- epi2: +b1b, scatter-add rows, count ----
        #pragma unroll
        for (int s = 0; s < 2; s++) {
            #pragma unroll
            for (int rh = 0; rh < 2; rh++) {
                int e = p * 32 + s * 16 + rh * 8 + r4;
                int r = rowI[base + e];
                if (q == 0 && (lane & 3) == 0) atomicAdd(&g_cnt[r], 1.0f);
                float* dst = g_sums + (size_t)r * 64;
                #pragma unroll
                for (int j = 0; j < 2; j++) {
                    int c0 = q * 16 + j * 8 + c2;
                    float x0 = acc2[s][j][rh * 2]     + sb1b[c0];
                    float x1 = acc2[s][j][rh * 2 + 1] + sb1b[c0 + 1];
                    REDV2(dst + c0, x0, x1);
                }
            }
        }
    }
}

// ============================== NODE KERNEL ==================================
// 64-node tiles. smem: b2a 512 | b2b 256 | br 256 | inv 256 -> 1280
// Ahi 17408 | Alo 17408 | Hhi 17408 | Hlo 17408 | W2aHi 34816 | W2aLo 34816
// | W2bHi 17408 | W2bLo 17408 | WrHi 17408 | WrLo 17408
#define NO_AHI  1280
#define NO_ALO  18688
#define NO_HHI  36096
#define NO_HLO  53504
#define NO_WAHI 70912
#define NO_WALO 105728
#define NO_WBHI 140544
#define NO_WBLO 157952
#define NO_WRHI 175360
#define NO_WRLO 192768
#define SMEM_NODE 210176

__global__ __launch_bounds__(512, 1)
void node_kernel(const float* __restrict__ src,
                 const float* __restrict__ W2a, const float* __restrict__ b2a,
                 const float* __restrict__ W2b, const float* __restrict__ b2b,
                 const float* __restrict__ Wr,  const float* __restrict__ br,
                 float* __restrict__ out)
{
    extern __shared__ char sm[];
    float* sb2a = (float*)sm;
    float* sb2b = (float*)(sm + 512);
    float* sbr  = (float*)(sm + 768);
    float* sInv = (float*)(sm + 1024);
    char* sAhi = sm + NO_AHI;  char* sAlo = sm + NO_ALO;
    char* sHhi = sm + NO_HHI;  char* sHlo = sm + NO_HLO;
    char* sWaHi = sm + NO_WAHI; char* sWaLo = sm + NO_WALO;
    char* sWbHi = sm + NO_WBHI; char* sWbLo = sm + NO_WBLO;
    char* sWrHi = sm + NO_WRHI; char* sWrLo = sm + NO_WRLO;

    const int tid = threadIdx.x, lane = tid & 31, w = tid >> 5;
    stage_w(W2a, sWaHi, sWaLo, 128, 0);
    stage_w(W2b, sWbHi, sWbLo, 64, 0);
    stage_w(Wr,  sWrHi, sWrLo, 64, 1);   // k-halves swapped: A=[src|z] vs concat(z,src)
    if (tid < 128) sb2a[tid] = b2a[tid];
    if (tid < 64)  sb2b[tid] = b2b[tid];
    if (tid < 64)  sbr[tid]  = br[tid];

    const int p = w & 3, q = w >> 2;
    const int r4 = lane >> 2;
    const int cb = (lane & 3) * 4;
    const int c2 = (lane & 3) * 2;
    const int m0 = p * 16;

    const int ntiles = (NN + 63) / 64;   // 782
    for (int t = blockIdx.x; t < ntiles; t += gridDim.x) {
        const int base = t * 64;
        __syncthreads();
        if (tid < 64) {
            int gn = base + tid;
            float c = (gn < NN) ? g_cnt[gn] : 1.0f;
            sInv[tid] = 1.0f / fmaxf(c, 1.0f);
        }
        __syncthreads();

        // ---- stage A = [src | agg] ----
        #pragma unroll
        for (int i = 0; i < 8; i++) {
            int idx = i * 512 + tid;
            int n = idx >> 6, kp = idx & 63;
            int gn = base + n;
            float2 v = make_float2(0.f, 0.f);
            if (gn < NN) {
                if (kp < 32) v = *(const float2*)(src + (size_t)gn * 64 + kp * 2);
                else {
                    float2 s2 = *(const float2*)(g_sums + (size_t)gn * 64 + (kp - 32) * 2);
                    float iv = sInv[n];
                    v = make_float2(s2.x * iv, s2.y * iv);
                }
            }
            uint32_t l32, h32 = pack_split(v, &l32);
            *(uint32_t*)(sAhi + n * XB + kp * 4) = h32;
            *(uint32_t*)(sAlo + n * XB + kp * 4) = l32;
        }
        __syncthreads();

        // ---- GEMM1: h = A @ W2a^T  (1 strip x 4 n8-tiles) ----
        float acc[4][4];
        #pragma unroll
        for (int j = 0; j < 4; j++) { acc[j][0]=0.f; acc[j][1]=0.f; acc[j][2]=0.f; acc[j][3]=0.f; }
        #pragma unroll
        for (int k0 = 0; k0 < 8; k0++) {
            int kb = k0 * 32 + cb;
            uint32_t ah[4], al[4];
            ldA(ah, sAhi, m0 + r4, kb);
            ldA(al, sAlo, m0 + r4, kb);
            #pragma unroll
            for (int j = 0; j < 4; j++) {
                int n0 = q * 32 + j * 8 + r4;
                uint32_t bh[2], bl[2];
                ldB(bh, sWaHi, n0, kb);
                ldB(bl, sWaLo, n0, kb);
                mma_bf16(acc[j], ah, bh);
                mma_bf16(acc[j], al, bh);
                mma_bf16(acc[j], ah, bl);
            }
        }
        // epi1 -> sH (distinct buffer; no hazard with concurrent GEMM1 readers)
        #pragma unroll
        for (int j = 0; j < 4; j++) {
            int c0 = q * 32 + j * 8 + c2;
            float bx = sb2a[c0], by = sb2a[c0 + 1];
            float2 v0 = make_float2(fmaxf(acc[j][0] + bx, 0.f), fmaxf(acc[j][1] + by, 0.f));
            float2 v1 = make_float2(fmaxf(acc[j][2] + bx, 0.f), fmaxf(acc[j][3] + by, 0.f));
            uint32_t l32, h32;
            h32 = pack_split(v0, &l32);
            *(uint32_t*)(sHhi + (m0 + r4) * XB + c0 * 2) = h32;
            *(uint32_t*)(sHlo + (m0 + r4) * XB + c0 * 2) = l32;
            h32 = pack_split(v1, &l32);
            *(uint32_t*)(sHhi + (m0 + 8 + r4) * XB + c0 * 2) = h32;
            *(uint32_t*)(sHlo + (m0 + 8 + r4) * XB + c0 * 2) = l32;
        }
        __syncthreads();

        // ---- GEMM2: z = h @ W2b^T (1 strip x 2 n8-tiles) ----
        float acc2[2][4];
        #pragma unroll
        for (int j = 0; j < 2; j++) { acc2[j][0]=0.f; acc2[j][1]=0.f; acc2[j][2]=0.f; acc2[j][3]=0.f; }
        #pragma unroll
        for (int k0 = 0; k0 < 8; k0++) {
            int kb = k0 * 32 + cb;
            uint32_t ah[4], al[4];
            ldA(ah, sHhi, m0 + r4, kb);
            ldA(al, sHlo, m0 + r4, kb);
            #pragma unroll
            for (int j = 0; j < 2; j++) {
                int n0 = q * 16 + j * 8 + r4;
                uint32_t bh[2], bl[2];
                ldB(bh, sWbHi, n0, kb);
                ldB(bl, sWbLo, n0, kb);
                mma_bf16(acc2[j], ah, bh);
                mma_bf16(acc2[j], al, bh);
                mma_bf16(acc2[j], ah, bl);
            }
        }
        // epi2: z (+b2b) -> sA cols 64..127 (A becomes [src|z])
        #pragma unroll
        for (int j = 0; j < 2; j++) {
            int c0 = q * 16 + j * 8 + c2;
            float bx = sb2b[c0], by = sb2b[c0 + 1];
            float2 v0 = make_float2(acc2[j][0] + bx, acc2[j][1] + by);
            float2 v1 = make_float2(acc2[j][2] + bx, acc2[j][3] + by);
            uint32_t l32, h32;
            h32 = pack_split(v0, &l32);
            *(uint32_t*)(sAhi + (m0 + r4) * XB + (64 + c0) * 2) = h32;
            *(uint32_t*)(sAlo + (m0 + r4) * XB + (64 + c0) * 2) = l32;
            h32 = pack_split(v1, &l32);
            *(uint32_t*)(sAhi + (m0 + 8 + r4) * XB + (64 + c0) * 2) = h32;
            *(uint32_t*)(sAlo + (m0 + 8 + r4) * XB + (64 + c0) * 2) = l32;
        }
        __syncthreads();

        // ---- GEMM3: out = [src|z] @ WrPerm^T ----
        float acc3[2][4];
        #pragma unroll
        for (int j = 0; j < 2; j++) { acc3[j][0]=0.f; acc3[j][1]=0.f; acc3[j][2]=0.f; acc3[j][3]=0.f; }
        #pragma unroll
        for (int k0 = 0; k0 < 8; k0++) {
            int kb = k0 * 32 + cb;
            uint32_t ah[4], al[4];
            ldA(ah, sAhi, m0 + r4, kb);
            ldA(al, sAlo, m0 + r4, kb);
            #pragma unroll
            for (int j = 0; j < 2; j++) {
                int n0 = q * 16 + j * 8 + r4;
                uint32_t bh[2], bl[2];
                ldB(bh, sWrHi, n0, kb);
                ldB(bl, sWrLo, n0, kb);
                mma_bf16(acc3[j], ah, bh);
                mma_bf16(acc3[j], al, bh);
                mma_bf16(acc3[j], ah, bl);
            }
        }
        // epi3: + br -> out
        #pragma unroll
        for (int rh = 0; rh < 2; rh++) {
            int gn = base + m0 + rh * 8 + r4;
            if (gn < NN) {
                #pragma unroll
                for (int j = 0; j < 2; j++) {
                    int c0 = q * 16 + j * 8 + c2;
                    float2 o = make_float2(acc3[j][rh * 2] + sbr[c0],
                                           acc3[j][rh * 2 + 1] + sbr[c0 + 1]);
                    *(float2*)(out + (size_t)gn * 64 + c0) = o;
                }
            }
        }
    }
}

// ---------------------------------------------------------------------------
extern "C" void kernel_launch(void* const* d_in, const int* in_sizes, int n_in,
                              void* d_out, int out_size) {
    const float* src   = (const float*)d_in[0];
    const int*   eidx  = (const int*)d_in[1];
    const float* eattr = (const float*)d_in[2];
    const float* W1a = (const float*)d_in[5];
    const float* b1a = (const float*)d_in[6];
    const float* W1b = (const float*)d_in[7];
    const float* b1b = (const float*)d_in[8];
    const float* W2a = (const float*)d_in[9];
    const float* b2a = (const float*)d_in[10];
    const float* W2b = (const float*)d_in[11];
    const float* b2b = (const float*)d_in[12];
    const float* Wr  = (const float*)d_in[13];
    const float* br  = (const float*)d_in[14];
    float* out = (float*)d_out;

    cudaFuncSetAttribute(edge_kernel, cudaFuncAttributeMaxDynamicSharedMemorySize, SMEM_EDGE);
    cudaFuncSetAttribute(node_kernel, cudaFuncAttributeMaxDynamicSharedMemorySize, SMEM_NODE);

    zero_kernel<<<(NN * 64 + 255) / 256, 256>>>();
    edge_kernel<<<148, 512, SMEM_EDGE>>>(src, eidx, eattr, W1a, b1a, W1b, b1b);
    node_kernel<<<148, 512, SMEM_NODE>>>(src, W2a, b2a, W2b, b2b, Wr, br, out);
}

// round 5
// speedup vs baseline: 1.6305x; 1.1515x over previous
#include <cuda_runtime.h>
#include <cstdint>

#define NN 50000
#define NE 800000
#define XW 132          // floats per smem row (128 + 4 pad): conflict-free frags
#define XB (XW * 4)     // 528 bytes

__device__ __align__(16) float g_sums[NN * 64];
__device__ __align__(16) float g_cnt[NN];

__global__ void zero_kernel() {
    int i = blockIdx.x * blockDim.x + threadIdx.x;
    float4 z = make_float4(0.f, 0.f, 0.f, 0.f);
    if (i < NN * 16) ((float4*)g_sums)[i] = z;
    if (i < NN / 4 + 1 && i * 4 + 3 < NN) ((float4*)g_cnt)[i] = z;
    if (i < 4) g_cnt[NN - 1 - i] = 0.f;   // tail (NN%4 coverage, idempotent)
}

__device__ __forceinline__ float to_tf32(float x) {
    float y;
    asm("cvt.rna.tf32.f32 %0, %1;" : "=f"(y) : "f"(x));
    return y;
}

__device__ __forceinline__ void mma_tf32(float d[4], const uint32_t a[4], const uint32_t b[2]) {
    asm volatile(
        "mma.sync.aligned.m16n8k8.row.col.f32.tf32.tf32.f32 "
        "{%0,%1,%2,%3}, {%4,%5,%6,%7}, {%8,%9}, {%0,%1,%2,%3};"
        : "+f"(d[0]), "+f"(d[1]), "+f"(d[2]), "+f"(d[3])
        : "r"(a[0]), "r"(a[1]), "r"(a[2]), "r"(a[3]), "r"(b[0]), "r"(b[1]));
}

// A fragment (row-major 16x8 tf32): p = buf + row*XB + k0*32 + (lane&3)*4
__device__ __forceinline__ void ldA(uint32_t a[4], const char* p) {
    a[0] = *(const uint32_t*)p;
    a[1] = *(const uint32_t*)(p + 8 * XB);
    a[2] = *(const uint32_t*)(p + 16);
    a[3] = *(const uint32_t*)(p + 8 * XB + 16);
}
// B fragment (k8 x n8, weight stored [n][k] row-major): p = buf + n*XB + k0*32 + (lane&3)*4
__device__ __forceinline__ void ldB(uint32_t b[2], const char* p) {
    b[0] = *(const uint32_t*)p;
    b[1] = *(const uint32_t*)(p + 16);
}

#define REDV2(ptr, x0, x1) \
    asm volatile("red.global.add.v2.f32 [%0], {%1,%2};" :: "l"(ptr), "f"(x0), "f"(x1) : "memory")

// stage fp32 weight [R][128] -> tf32-rounded fp32 smem [R][XW], optional k-half swap
__device__ __forceinline__ void stage_w(const float* __restrict__ W, char* dst, int R, int swap) {
    for (int idx = threadIdx.x; idx < R * 64; idx += 512) {
        int r = idx >> 6, kp2 = idx & 63;
        float2 v = *(const float2*)(W + r * 128 + kp2 * 2);
        v.x = to_tf32(v.x); v.y = to_tf32(v.y);
        int kd = swap ? (kp2 ^ 32) : kp2;
        *(float2*)(dst + r * XB + kd * 8) = v;
    }
}

// ============================== EDGE KERNEL ==================================
// smem: b1a 512 | b1b 256 | col 512 = 1280 | X 67584 | Wa 67584 | Wb 33792
#define EO_X   1280
#define EO_WA  (EO_X + 128 * XB)
#define EO_WB  (EO_WA + 128 * XB)
#define SMEM_EDGE (EO_WB + 64 * XB)

__global__ __launch_bounds__(512, 1)
void edge_kernel(const float* __restrict__ src, const int* __restrict__ eidx,
                 const float* __restrict__ eattr,
                 const float* __restrict__ W1a, const float* __restrict__ b1a,
                 const float* __restrict__ W1b, const float* __restrict__ b1b)
{
    extern __shared__ char sm[];
    float* sb1a = (float*)sm;
    float* sb1b = (float*)(sm + 512);
    int*   sCol = (int*)(sm + 768);
    char* sX  = sm + EO_X;
    char* sWa = sm + EO_WA;
    char* sWb = sm + EO_WB;

    const int tid = threadIdx.x, lane = tid & 31, w = tid >> 5;
    stage_w(W1a, sWa, 128, 0);
    stage_w(W1b, sWb, 64, 0);
    if (tid < 128) sb1a[tid] = b1a[tid];
    if (tid < 64)  sb1b[tid] = b1b[tid];

    const int* rowI = eidx;        // int32 (jax x64 disabled)
    const int* colI = eidx + NE;
    const int p = w & 3, q = w >> 2;
    const int r4 = lane >> 2;
    const int cb = (lane & 3) * 4;
    const int c2 = (lane & 3) * 2;

    for (int t = blockIdx.x; t < NE / 128; t += gridDim.x) {
        const int base = t * 128;
        __syncthreads();
        if (tid < 128) sCol[tid] = colI[base + tid];
        __syncthreads();

        // ---- stage X = [src[col] | eattr] (tf32-rounded fp32) ----
        #pragma unroll
        for (int i = 0; i < 16; i++) {
            int idx = i * 512 + tid;
            int e = idx >> 6, kp2 = idx & 63;
            const float* ptr = (kp2 < 32) ? src + (size_t)sCol[e] * 64 + kp2 * 2
                                          : eattr + (size_t)(base + e) * 64 + (kp2 - 32) * 2;
            float2 v = *(const float2*)ptr;
            v.x = to_tf32(v.x); v.y = to_tf32(v.y);
            *(float2*)(sX + e * XB + kp2 * 8) = v;
        }
        __syncthreads();

        // ---- GEMM1: h = X @ W1a^T (2 m-strips x 4 n8-tiles, k0=16 x k8) ----
        float acc[2][4][4];
        #pragma unroll
        for (int s = 0; s < 2; s++)
            #pragma unroll
            for (int j = 0; j < 4; j++)
                { acc[s][j][0]=0.f; acc[s][j][1]=0.f; acc[s][j][2]=0.f; acc[s][j][3]=0.f; }

        #pragma unroll
        for (int k0 = 0; k0 < 16; k0++) {
            int kb = k0 * 32 + cb;
            uint32_t a[2][4];
            ldA(a[0], sX + (p * 32 + r4) * XB + kb);
            ldA(a[1], sX + (p * 32 + 16 + r4) * XB + kb);
            #pragma unroll
            for (int j = 0; j < 4; j++) {
                uint32_t b[2];
                ldB(b, sWa + (q * 32 + j * 8 + r4) * XB + kb);
                mma_tf32(acc[0][j], a[0], b);
                mma_tf32(acc[1][j], a[1], b);
            }
        }
        __syncthreads();   // all warps done reading X

        // ---- epi1: relu(+b1a), tf32-round -> overwrite X rows ----
        #pragma unroll
        for (int s = 0; s < 2; s++) {
            int r0 = p * 32 + s * 16 + r4;
            #pragma unroll
            for (int j = 0; j < 4; j++) {
                int c0 = q * 32 + j * 8 + c2;
                float bx = sb1a[c0], by = sb1a[c0 + 1];
                float2 v0, v1;
                v0.x = to_tf32(fmaxf(acc[s][j][0] + bx, 0.f));
                v0.y = to_tf32(fmaxf(acc[s][j][1] + by, 0.f));
                v1.x = to_tf32(fmaxf(acc[s][j][2] + bx, 0.f));
                v1.y = to_tf32(fmaxf(acc[s][j][3] + by, 0.f));
                *(float2*)(sX + r0 * XB + c0 * 4) = v0;
                *(float2*)(sX + (r0 + 8) * XB + c0 * 4) = v1;
            }
        }
        __syncthreads();

        // ---- GEMM2: D2 = h @ W1b^T (2 strips x 2 n8-tiles) ----
        float acc2[2][2][4];
        #pragma unroll
        for (int s = 0; s < 2; s++)
            #pragma unroll
            for (int j = 0; j < 2; j++)
                { acc2[s][j][0]=0.f; acc2[s][j][1]=0.f; acc2[s][j][2]=0.f; acc2[s][j][3]=0.f; }

        #pragma unroll
        for (int k0 = 0; k0 < 16; k0++) {
            int kb = k0 * 32 + cb;
            uint32_t a[2][4];
            ldA(a[0], sX + (p * 32 + r4) * XB + kb);
            ldA(a[1], sX + (p * 32 + 16 + r4) * XB + kb);
            #pragma unroll
            for (int j = 0; j < 2; j++) {
                uint32_t b[2];
                ldB(b, sWb + (q * 16 + j * 8 + r4) * XB + kb);
                mma_tf32(acc2[0][j], a[0], b);
                mma_tf32(acc2[1][j], a[1], b);
            }
        }

        // ---- epi2: +b1b, scatter-add, count ----
        #pragma unroll
        for (int s = 0; s < 2; s++) {
            #pragma unroll
            for (int rh = 0; rh < 2; rh++) {
                int e = p * 32 + s * 16 + rh * 8 + r4;
                int r = rowI[base + e];
                if (q == 0 && (lane & 3) == 0) atomicAdd(&g_cnt[r], 1.0f);
                float* dst = g_sums + (size_t)r * 64;
                #pragma unroll
                for (int j = 0; j < 2; j++) {
                    int c0 = q * 16 + j * 8 + c2;
                    REDV2(dst + c0,
                          acc2[s][j][rh * 2]     + sb1b[c0],
                          acc2[s][j][rh * 2 + 1] + sb1b[c0 + 1]);
                }
            }
        }
    }
}

// ============================== NODE KERNEL ==================================
// smem: b2a 512 | b2b 256 | br 256 | inv 256 = 1280
// A 33792 | H 33792 | W2a 67584 | W2b 33792 | Wr 33792
#define NO_A   1280
#define NO_H   (NO_A + 64 * XB)
#define NO_WA  (NO_H + 64 * XB)
#define NO_WB  (NO_WA + 128 * XB)
#define NO_WR  (NO_WB + 64 * XB)
#define SMEM_NODE (NO_WR + 64 * XB)

__global__ __launch_bounds__(512, 1)
void node_kernel(const float* __restrict__ src,
                 const float* __restrict__ W2a, const float* __restrict__ b2a,
                 const float* __restrict__ W2b, const float* __restrict__ b2b,
                 const float* __restrict__ Wr,  const float* __restrict__ br,
                 float* __restrict__ out)
{
    extern __shared__ char sm[];
    float* sb2a = (float*)sm;
    float* sb2b = (float*)(sm + 512);
    float* sbr  = (float*)(sm + 768);
    float* sInv = (float*)(sm + 1024);
    char* sA  = sm + NO_A;
    char* sH  = sm + NO_H;
    char* sWa = sm + NO_WA;
    char* sWb = sm + NO_WB;
    char* sWr = sm + NO_WR;

    const int tid = threadIdx.x, lane = tid & 31, w = tid >> 5;
    stage_w(W2a, sWa, 128, 0);
    stage_w(W2b, sWb, 64, 0);
    stage_w(Wr,  sWr, 64, 1);   // k-halves swapped: A=[src|z] vs concat(z,src)
    if (tid < 128) sb2a[tid] = b2a[tid];
    if (tid < 64)  sb2b[tid] = b2b[tid];
    if (tid < 64)  sbr[tid]  = br[tid];

    const int p = w & 3, q = w >> 2;
    const int r4 = lane >> 2;
    const int cb = (lane & 3) * 4;
    const int c2 = (lane & 3) * 2;
    const int m0 = p * 16;

    const int ntiles = (NN + 63) / 64;   // 782
    for (int t = blockIdx.x; t < ntiles; t += gridDim.x) {
        const int base = t * 64;
        __syncthreads();
        if (tid < 64) {
            int gn = base + tid;
            float c = (gn < NN) ? g_cnt[gn] : 1.0f;
            sInv[tid] = 1.0f / fmaxf(c, 1.0f);
        }
        __syncthreads();

        // ---- stage A = [src | agg] ----
        #pragma unroll
        for (int i = 0; i < 8; i++) {
            int idx = i * 512 + tid;
            int n = idx >> 6, kp2 = idx & 63;
            int gn = base + n;
            float2 v = make_float2(0.f, 0.f);
            if (gn < NN) {
                if (kp2 < 32) v = *(const float2*)(src + (size_t)gn * 64 + kp2 * 2);
                else {
                    float2 s2 = *(const float2*)(g_sums + (size_t)gn * 64 + (kp2 - 32) * 2);
                    float iv = sInv[n];
                    v = make_float2(s2.x * iv, s2.y * iv);
                }
            }
            v.x = to_tf32(v.x); v.y = to_tf32(v.y);
            *(float2*)(sA + n * XB + kp2 * 8) = v;
        }
        __syncthreads();

        // ---- GEMM1: h = A @ W2a^T (1 strip x 4 n8-tiles) ----
        float acc[4][4];
        #pragma unroll
        for (int j = 0; j < 4; j++) { acc[j][0]=0.f; acc[j][1]=0.f; acc[j][2]=0.f; acc[j][3]=0.f; }
        #pragma unroll
        for (int k0 = 0; k0 < 16; k0++) {
            int kb = k0 * 32 + cb;
            uint32_t a[4];
            ldA(a, sA + (m0 + r4) * XB + kb);
            #pragma unroll
            for (int j = 0; j < 4; j++) {
                uint32_t b[2];
                ldB(b, sWa + (q * 32 + j * 8 + r4) * XB + kb);
                mma_tf32(acc[j], a, b);
            }
        }
        // epi1 -> sH (distinct buffer)
        #pragma unroll
        for (int j = 0; j < 4; j++) {
            int c0 = q * 32 + j * 8 + c2;
            float bx = sb2a[c0], by = sb2a[c0 + 1];
            float2 v0, v1;
            v0.x = to_tf32(fmaxf(acc[j][0] + bx, 0.f));
            v0.y = to_tf32(fmaxf(acc[j][1] + by, 0.f));
            v1.x = to_tf32(fmaxf(acc[j][2] + bx, 0.f));
            v1.y = to_tf32(fmaxf(acc[j][3] + by, 0.f));
            *(float2*)(sH + (m0 + r4) * XB + c0 * 4) = v0;
            *(float2*)(sH + (m0 + 8 + r4) * XB + c0 * 4) = v1;
        }
        __syncthreads();

        // ---- GEMM2: z = h @ W2b^T (1 strip x 2 n8-tiles) ----
        float acc2[2][4];
        #pragma unroll
        for (int j = 0; j < 2; j++) { acc2[j][0]=0.f; acc2[j][1]=0.f; acc2[j][2]=0.f; acc2[j][3]=0.f; }
        #pragma unroll
        for (int k0 = 0; k0 < 16; k0++) {
            int kb = k0 * 32 + cb;
            uint32_t a[4];
            ldA(a, sH + (m0 + r4) * XB + kb);
            #pragma unroll
            for (int j = 0; j < 2; j++) {
                uint32_t b[2];
                ldB(b, sWb + (q * 16 + j * 8 + r4) * XB + kb);
                mma_tf32(acc2[j], a, b);
            }
        }
        // epi2: z (+b2b) -> sA cols 64..127
        #pragma unroll
        for (int j = 0; j < 2; j++) {
            int c0 = q * 16 + j * 8 + c2;
            float bx = sb2b[c0], by = sb2b[c0 + 1];
            float2 v0, v1;
            v0.x = to_tf32(acc2[j][0] + bx);
            v0.y = to_tf32(acc2[j][1] + by);
            v1.x = to_tf32(acc2[j][2] + bx);
            v1.y = to_tf32(acc2[j][3] + by);
            *(float2*)(sA + (m0 + r4) * XB + (64 + c0) * 4) = v0;
            *(float2*)(sA + (m0 + 8 + r4) * XB + (64 + c0) * 4) = v1;
        }
        __syncthreads();

        // ---- GEMM3: out = [src|z] @ WrPerm^T ----
        float acc3[2][4];
        #pragma unroll
        for (int j = 0; j < 2; j++) { acc3[j][0]=0.f; acc3[j][1]=0.f; acc3[j][2]=0.f; acc3[j][3]=0.f; }
        #pragma unroll
        for (int k0 = 0; k0 < 16; k0++) {
            int kb = k0 * 32 + cb;
            uint32_t a[4];
            ldA(a, sA + (m0 + r4) * XB + kb);
            #pragma unroll
            for (int j = 0; j < 2; j++) {
                uint32_t b[2];
                ldB(b, sWr + (q * 16 + j * 8 + r4) * XB + kb);
                mma_tf32(acc3[j], a, b);
            }
        }
        // epi3: + br -> out
        #pragma unroll
        for (int rh = 0; rh < 2; rh++) {
            int gn = base + m0 + rh * 8 + r4;
            if (gn < NN) {
                #pragma unroll
                for (int j = 0; j < 2; j++) {
                    int c0 = q * 16 + j * 8 + c2;
                    float2 o = make_float2(acc3[j][rh * 2] + sbr[c0],
                                           acc3[j][rh * 2 + 1] + sbr[c0 + 1]);
                    *(float2*)(out + (size_t)gn * 64 + c0) = o;
                }
            }
        }
    }
}

// ---------------------------------------------------------------------------
extern "C" void kernel_launch(void* const* d_in, const int* in_sizes, int n_in,
                              void* d_out, int out_size) {
    const float* src   = (const float*)d_in[0];
    const int*   eidx  = (const int*)d_in[1];
    const float* eattr = (const float*)d_in[2];
    const float* W1a = (const float*)d_in[5];
    const float* b1a = (const float*)d_in[6];
    const float* W1b = (const float*)d_in[7];
    const float* b1b = (const float*)d_in[8];
    const float* W2a = (const float*)d_in[9];
    const float* b2a = (const float*)d_in[10];
    const float* W2b = (const float*)d_in[11];
    const float* b2b = (const float*)d_in[12];
    const float* Wr  = (const float*)d_in[13];
    const float* br  = (const float*)d_in[14];
    float* out = (float*)d_out;

    cudaFuncSetAttribute(edge_kernel, cudaFuncAttributeMaxDynamicSharedMemorySize, SMEM_EDGE);
    cudaFuncSetAttribute(node_kernel, cudaFuncAttributeMaxDynamicSharedMemorySize, SMEM_NODE);

    zero_kernel<<<(NN * 16 + 255) / 256, 256>>>();
    edge_kernel<<<148, 512, SMEM_EDGE>>>(src, eidx, eattr, W1a, b1a, W1b, b1b);
    node_kernel<<<148, 512, SMEM_NODE>>>(src, W2a, b2a, W2b, b2b, Wr, br, out);
}

// round 6
// speedup vs baseline: 2.7546x; 1.6894x over previous
#include <cuda_runtime.h>
#include <cstdint>

#define NN 50000
#define NE 800000

__device__ __align__(16) float g_sums[NN * 64];
__device__ __align__(16) float g_cnt[NN];
__device__ __align__(16) float g_P[NN * 128];   // P = src @ W1aL^T + b1a (fp32)

__global__ void zero_kernel() {
    int i = blockIdx.x * blockDim.x + threadIdx.x;
    float4 z = make_float4(0.f, 0.f, 0.f, 0.f);
    if (i < NN * 16) ((float4*)g_sums)[i] = z;
    if (i < NN / 4 + 1 && i * 4 + 3 < NN) ((float4*)g_cnt)[i] = z;
    if (i < 4) g_cnt[NN - 1 - i] = 0.f;
}

__device__ __forceinline__ float to_tf32(float x) {
    float y;
    asm("cvt.rna.tf32.f32 %0, %1;" : "=f"(y) : "f"(x));
    return y;
}

__device__ __forceinline__ void mma_tf32(float d[4], const uint32_t a[4], const uint32_t b[2]) {
    asm volatile(
        "mma.sync.aligned.m16n8k8.row.col.f32.tf32.tf32.f32 "
        "{%0,%1,%2,%3}, {%4,%5,%6,%7}, {%8,%9}, {%0,%1,%2,%3};"
        : "+f"(d[0]), "+f"(d[1]), "+f"(d[2]), "+f"(d[3])
        : "r"(a[0]), "r"(a[1]), "r"(a[2]), "r"(a[3]), "r"(b[0]), "r"(b[1]));
}

// A fragment (row-major 16x8 tf32), row stride `stride` bytes
__device__ __forceinline__ void ldA_s(uint32_t a[4], const char* p, int stride) {
    a[0] = *(const uint32_t*)p;
    a[1] = *(const uint32_t*)(p + 8 * stride);
    a[2] = *(const uint32_t*)(p + 16);
    a[3] = *(const uint32_t*)(p + 8 * stride + 16);
}
__device__ __forceinline__ void ldB(uint32_t b[2], const char* p) {
    b[0] = *(const uint32_t*)p;
    b[1] = *(const uint32_t*)(p + 16);
}

#define REDV2(ptr, x0, x1) \
    asm volatile("red.global.add.v2.f32 [%0], {%1,%2};" :: "l"(ptr), "f"(x0), "f"(x1) : "memory")

// row widths (floats): 68 for K=64 tiles, 132 for K=128 tiles (both %32==4: conflict-free)
#define W68  272
#define W132 528

// ============================ P kernel =======================================
// P[n] = src[n] @ W1aL^T + b1a   (N=128 outputs, K=64), 64-node tiles, 256 thr
// smem: sA 64x68f = 17408 | sW 128x68f = 34816
#define PO_A 0
#define PO_W 17408
#define SMEM_P (PO_W + 34816)

__global__ __launch_bounds__(256, 2)
void p_kernel(const float* __restrict__ src, const float* __restrict__ W1a,
              const float* __restrict__ b1a)
{
    extern __shared__ char sm[];
    char* sA = sm + PO_A;
    char* sW = sm + PO_W;
    const int tid = threadIdx.x, lane = tid & 31, w = tid >> 5;
    const int p = w & 1, q = w >> 1;
    const int r4 = lane >> 2, cb = (lane & 3) * 4, c2 = (lane & 3) * 2;

    // stage W1aL (cols 0..63 of W1a[128][128]) as tf32
    for (int idx = tid; idx < 128 * 32; idx += 256) {
        int r = idx >> 5, kp2 = idx & 31;
        float2 v = *(const float2*)(W1a + r * 128 + kp2 * 2);
        v.x = to_tf32(v.x); v.y = to_tf32(v.y);
        *(float2*)(sW + r * W68 + kp2 * 8) = v;
    }

    const int base = blockIdx.x * 64;
    // stage src tile (tf32)
    for (int idx = tid; idx < 64 * 32; idx += 256) {
        int n = idx >> 5, kp2 = idx & 31;
        int gn = base + n;
        float2 v = make_float2(0.f, 0.f);
        if (gn < NN) v = *(const float2*)(src + (size_t)gn * 64 + kp2 * 2);
        v.x = to_tf32(v.x); v.y = to_tf32(v.y);
        *(float2*)(sA + n * W68 + kp2 * 8) = v;
    }
    __syncthreads();

    float acc[2][4][4];
    #pragma unroll
    for (int s = 0; s < 2; s++)
        #pragma unroll
        for (int j = 0; j < 4; j++)
            { acc[s][j][0]=0.f; acc[s][j][1]=0.f; acc[s][j][2]=0.f; acc[s][j][3]=0.f; }

    #pragma unroll
    for (int k0 = 0; k0 < 8; k0++) {
        int kb = k0 * 32 + cb;
        uint32_t a[2][4];
        ldA_s(a[0], sA + (p * 32 + r4) * W68 + kb, W68);
        ldA_s(a[1], sA + (p * 32 + 16 + r4) * W68 + kb, W68);
        #pragma unroll
        for (int j = 0; j < 4; j++) {
            uint32_t b[2];
            ldB(b, sW + (q * 32 + j * 8 + r4) * W68 + kb);
            mma_tf32(acc[0][j], a[0], b);
            mma_tf32(acc[1][j], a[1], b);
        }
    }

    #pragma unroll
    for (int s = 0; s < 2; s++) {
        #pragma unroll
        for (int rh = 0; rh < 2; rh++) {
            int gn = base + p * 32 + s * 16 + rh * 8 + r4;
            if (gn < NN) {
                #pragma unroll
                for (int j = 0; j < 4; j++) {
                    int c0 = q * 32 + j * 8 + c2;
                    float2 o;
                    o.x = acc[s][j][rh * 2]     + __ldg(b1a + c0);
                    o.y = acc[s][j][rh * 2 + 1] + __ldg(b1a + c0 + 1);
                    *(float2*)(g_P + (size_t)gn * 128 + c0) = o;
                }
            }
        }
    }
}

// ============================ EDGE KERNEL ====================================
// 64-edge tiles, 256 threads, 2 CTAs/SM.
// h1 = relu(P[col] + eattr @ W1aR^T); D2 = h1 @ W1b^T + b1b; scatter-add.
// smem: col 256 | row 256 | b1b 256 | XH 64x132f 33792 | WaR 128x68f 34816 | Wb 64x132f 33792
#define EO_COL 0
#define EO_ROW 256
#define EO_B1B 512
#define EO_XH  768
#define EO_WA  (EO_XH + 64 * W132)
#define EO_WB  (EO_WA + 128 * W68)
#define SMEM_EDGE (EO_WB + 64 * W132)   // 103168 B

__global__ __launch_bounds__(256, 2)
void edge_kernel(const int* __restrict__ eidx, const float* __restrict__ eattr,
                 const float* __restrict__ W1a, const float* __restrict__ W1b,
                 const float* __restrict__ b1b)
{
    extern __shared__ char sm[];
    int*   sCol = (int*)(sm + EO_COL);
    int*   sRow = (int*)(sm + EO_ROW);
    float* sb1b = (float*)(sm + EO_B1B);
    char* sXH = sm + EO_XH;
    char* sWa = sm + EO_WA;
    char* sWb = sm + EO_WB;

    const int tid = threadIdx.x, lane = tid & 31, w = tid >> 5;
    const int p = w & 1, q = w >> 1;          // p: 32-row strip, q: col group
    const int r4 = lane >> 2, cb = (lane & 3) * 4, c2 = (lane & 3) * 2;

    // stage W1aR (cols 64..127) and W1b (tf32)
    for (int idx = tid; idx < 128 * 32; idx += 256) {
        int r = idx >> 5, kp2 = idx & 31;
        float2 v = *(const float2*)(W1a + r * 128 + 64 + kp2 * 2);
        v.x = to_tf32(v.x); v.y = to_tf32(v.y);
        *(float2*)(sWa + r * W68 + kp2 * 8) = v;
    }
    for (int idx = tid; idx < 64 * 64; idx += 256) {
        int r = idx >> 6, kp2 = idx & 63;
        float2 v = *(const float2*)(W1b + r * 128 + kp2 * 2);
        v.x = to_tf32(v.x); v.y = to_tf32(v.y);
        *(float2*)(sWb + r * W132 + kp2 * 8) = v;
    }
    if (tid < 64) sb1b[tid] = b1b[tid];

    const int* rowI = eidx;        // int32 (jax x64 disabled)
    const int* colI = eidx + NE;

    for (int t = blockIdx.x; t < NE / 64; t += gridDim.x) {
        const int base = t * 64;
        __syncthreads();
        if (tid < 64) { sRow[tid] = rowI[base + tid]; sCol[tid] = colI[base + tid]; }
        // ---- stage eattr tile (64 x 64, tf32, coalesced) ----
        #pragma unroll
        for (int i = 0; i < 8; i++) {
            int idx = i * 256 + tid;
            int e = idx >> 5, kp2 = idx & 31;
            float2 v = *(const float2*)(eattr + (size_t)(base + e) * 64 + kp2 * 2);
            v.x = to_tf32(v.x); v.y = to_tf32(v.y);
            *(float2*)(sXH + e * W132 + kp2 * 8) = v;
        }
        __syncthreads();

        // ---- GEMM1: eattr @ W1aR^T (K=64: 8 k-steps) ----
        float acc[2][4][4];
        #pragma unroll
        for (int s = 0; s < 2; s++)
            #pragma unroll
            for (int j = 0; j < 4; j++)
                { acc[s][j][0]=0.f; acc[s][j][1]=0.f; acc[s][j][2]=0.f; acc[s][j][3]=0.f; }

        #pragma unroll
        for (int k0 = 0; k0 < 8; k0++) {
            int kb = k0 * 32 + cb;
            uint32_t a[2][4];
            ldA_s(a[0], sXH + (p * 32 + r4) * W132 + kb, W132);
            ldA_s(a[1], sXH + (p * 32 + 16 + r4) * W132 + kb, W132);
            #pragma unroll
            for (int j = 0; j < 4; j++) {
                uint32_t b[2];
                ldB(b, sWa + (q * 32 + j * 8 + r4) * W68 + kb);
                mma_tf32(acc[0][j], a[0], b);
                mma_tf32(acc[1][j], a[1], b);
            }
        }
        __syncthreads();   // done reading eattr from sXH

        // ---- epi1: h = relu(acc + P[col]) -> sXH (tf32) ----
        #pragma unroll
        for (int s = 0; s < 2; s++) {
            int r0 = p * 32 + s * 16 + r4;
            int cA = sCol[r0], cB = sCol[r0 + 8];
            #pragma unroll
            for (int j = 0; j < 4; j++) {
                int c0 = q * 32 + j * 8 + c2;
                float2 pa = *(const float2*)(g_P + (size_t)cA * 128 + c0);
                float2 pb = *(const float2*)(g_P + (size_t)cB * 128 + c0);
                float2 v0, v1;
                v0.x = to_tf32(fmaxf(acc[s][j][0] + pa.x, 0.f));
                v0.y = to_tf32(fmaxf(acc[s][j][1] + pa.y, 0.f));
                v1.x = to_tf32(fmaxf(acc[s][j][2] + pb.x, 0.f));
                v1.y = to_tf32(fmaxf(acc[s][j][3] + pb.y, 0.f));
                *(float2*)(sXH + r0 * W132 + c0 * 4) = v0;
                *(float2*)(sXH + (r0 + 8) * W132 + c0 * 4) = v1;
            }
        }
        __syncthreads();

        // ---- GEMM2: h @ W1b^T (K=128: 16 k-steps, N=64) ----
        float acc2[2][2][4];
        #pragma unroll
        for (int s = 0; s < 2; s++)
            #pragma unroll
            for (int j = 0; j < 2; j++)
                { acc2[s][j][0]=0.f; acc2[s][j][1]=0.f; acc2[s][j][2]=0.f; acc2[s][j][3]=0.f; }

        #pragma unroll
        for (int k0 = 0; k0 < 16; k0++) {
            int kb = k0 * 32 + cb;
            uint32_t a[2][4];
            ldA_s(a[0], sXH + (p * 32 + r4) * W132 + kb, W132);
            ldA_s(a[1], sXH + (p * 32 + 16 + r4) * W132 + kb, W132);
            #pragma unroll
            for (int j = 0; j < 2; j++) {
                uint32_t b[2];
                ldB(b, sWb + (q * 16 + j * 8 + r4) * W132 + kb);
                mma_tf32(acc2[0][j], a[0], b);
                mma_tf32(acc2[1][j], a[1], b);
            }
        }

        // ---- epi2: +b1b, scatter-add, count ----
        #pragma unroll
        for (int s = 0; s < 2; s++) {
            #pragma unroll
            for (int rh = 0; rh < 2; rh++) {
                int e = p * 32 + s * 16 + rh * 8 + r4;
                int r = sRow[e];
                if (q == 0 && (lane & 3) == 0) atomicAdd(&g_cnt[r], 1.0f);
                float* dst = g_sums + (size_t)r * 64;
                #pragma unroll
                for (int j = 0; j < 2; j++) {
                    int c0 = q * 16 + j * 8 + c2;
                    REDV2(dst + c0,
                          acc2[s][j][rh * 2]     + sb1b[c0],
                          acc2[s][j][rh * 2 + 1] + sb1b[c0 + 1]);
                }
            }
        }
    }
}

// ============================== NODE KERNEL ==================================
// (unchanged structure from R5: 64-node tiles, 512 threads)
#define XW 132
#define XB (XW * 4)
#define NO_A   1280
#define NO_H   (NO_A + 64 * XB)
#define NO_WA  (NO_H + 64 * XB)
#define NO_WB  (NO_WA + 128 * XB)
#define NO_WR  (NO_WB + 64 * XB)
#define SMEM_NODE (NO_WR + 64 * XB)

__device__ __forceinline__ void stage_w(const float* __restrict__ W, char* dst, int R, int swap) {
    for (int idx = threadIdx.x; idx < R * 64; idx += 512) {
        int r = idx >> 6, kp2 = idx & 63;
        float2 v = *(const float2*)(W + r * 128 + kp2 * 2);
        v.x = to_tf32(v.x); v.y = to_tf32(v.y);
        int kd = swap ? (kp2 ^ 32) : kp2;
        *(float2*)(dst + r * XB + kd * 8) = v;
    }
}

__global__ __launch_bounds__(512, 1)
void node_kernel(const float* __restrict__ src,
                 const float* __restrict__ W2a, const float* __restrict__ b2a,
                 const float* __restrict__ W2b, const float* __restrict__ b2b,
                 const float* __restrict__ Wr,  const float* __restrict__ br,
                 float* __restrict__ out)
{
    extern __shared__ char sm[];
    float* sb2a = (float*)sm;
    float* sb2b = (float*)(sm + 512);
    float* sbr  = (float*)(sm + 768);
    float* sInv = (float*)(sm + 1024);
    char* sA  = sm + NO_A;
    char* sH  = sm + NO_H;
    char* sWa = sm + NO_WA;
    char* sWb = sm + NO_WB;
    char* sWr = sm + NO_WR;

    const int tid = threadIdx.x, lane = tid & 31, w = tid >> 5;
    stage_w(W2a, sWa, 128, 0);
    stage_w(W2b, sWb, 64, 0);
    stage_w(Wr,  sWr, 64, 1);   // k-halves swapped: A=[src|z] vs concat(z,src)
    if (tid < 128) sb2a[tid] = b2a[tid];
    if (tid < 64)  sb2b[tid] = b2b[tid];
    if (tid < 64)  sbr[tid]  = br[tid];

    const int p = w & 3, q = w >> 2;
    const int r4 = lane >> 2, cb = (lane & 3) * 4, c2 = (lane & 3) * 2;
    const int m0 = p * 16;

    const int ntiles = (NN + 63) / 64;
    for (int t = blockIdx.x; t < ntiles; t += gridDim.x) {
        const int base = t * 64;
        __syncthreads();
        if (tid < 64) {
            int gn = base + tid;
            float c = (gn < NN) ? g_cnt[gn] : 1.0f;
            sInv[tid] = 1.0f / fmaxf(c, 1.0f);
        }
        __syncthreads();

        #pragma unroll
        for (int i = 0; i < 8; i++) {
            int idx = i * 512 + tid;
            int n = idx >> 6, kp2 = idx & 63;
            int gn = base + n;
            float2 v = make_float2(0.f, 0.f);
            if (gn < NN) {
                if (kp2 < 32) v = *(const float2*)(src + (size_t)gn * 64 + kp2 * 2);
                else {
                    float2 s2 = *(const float2*)(g_sums + (size_t)gn * 64 + (kp2 - 32) * 2);
                    float iv = sInv[n];
                    v = make_float2(s2.x * iv, s2.y * iv);
                }
            }
            v.x = to_tf32(v.x); v.y = to_tf32(v.y);
            *(float2*)(sA + n * XB + kp2 * 8) = v;
        }
        __syncthreads();

        float acc[4][4];
        #pragma unroll
        for (int j = 0; j < 4; j++) { acc[j][0]=0.f; acc[j][1]=0.f; acc[j][2]=0.f; acc[j][3]=0.f; }
        #pragma unroll
        for (int k0 = 0; k0 < 16; k0++) {
            int kb = k0 * 32 + cb;
            uint32_t a[4];
            ldA_s(a, sA + (m0 + r4) * XB + kb, XB);
            #pragma unroll
            for (int j = 0; j < 4; j++) {
                uint32_t b[2];
                ldB(b, sWa + (q * 32 + j * 8 + r4) * XB + kb);
                mma_tf32(acc[j], a, b);
            }
        }
        #pragma unroll
        for (int j = 0; j < 4; j++) {
            int c0 = q * 32 + j * 8 + c2;
            float bx = sb2a[c0], by = sb2a[c0 + 1];
            float2 v0, v1;
            v0.x = to_tf32(fmaxf(acc[j][0] + bx, 0.f));
            v0.y = to_tf32(fmaxf(acc[j][1] + by, 0.f));
            v1.x = to_tf32(fmaxf(acc[j][2] + bx, 0.f));
            v1.y = to_tf32(fmaxf(acc[j][3] + by, 0.f));
            *(float2*)(sH + (m0 + r4) * XB + c0 * 4) = v0;
            *(float2*)(sH + (m0 + 8 + r4) * XB + c0 * 4) = v1;
        }
        __syncthreads();

        float acc2[2][4];
        #pragma unroll
        for (int j = 0; j < 2; j++) { acc2[j][0]=0.f; acc2[j][1]=0.f; acc2[j][2]=0.f; acc2[j][3]=0.f; }
        #pragma unroll
        for (int k0 = 0; k0 < 16; k0++) {
            int kb = k0 * 32 + cb;
            uint32_t a[4];
            ldA_s(a, sH + (m0 + r4) * XB + kb, XB);
            #pragma unroll
            for (int j = 0; j < 2; j++) {
                uint32_t b[2];
                ldB(b, sWb + (q * 16 + j * 8 + r4) * XB + kb);
                mma_tf32(acc2[j], a, b);
            }
        }
        #pragma unroll
        for (int j = 0; j < 2; j++) {
            int c0 = q * 16 + j * 8 + c2;
            float bx = sb2b[c0], by = sb2b[c0 + 1];
            float2 v0, v1;
            v0.x = to_tf32(acc2[j][0] + bx);
            v0.y = to_tf32(acc2[j][1] + by);
            v1.x = to_tf32(acc2[j][2] + bx);
            v1.y = to_tf32(acc2[j][3] + by);
            *(float2*)(sA + (m0 + r4) * XB + (64 + c0) * 4) = v0;
            *(float2*)(sA + (m0 + 8 + r4) * XB + (64 + c0) * 4) = v1;
        }
        __syncthreads();

        float acc3[2][4];
        #pragma unroll
        for (int j = 0; j < 2; j++) { acc3[j][0]=0.f; acc3[j][1]=0.f; acc3[j][2]=0.f; acc3[j][3]=0.f; }
        #pragma unroll
        for (int k0 = 0; k0 < 16; k0++) {
            int kb = k0 * 32 + cb;
            uint32_t a[4];
            ldA_s(a, sA + (m0 + r4) * XB + kb, XB);
            #pragma unroll
            for (int j = 0; j < 2; j++) {
                uint32_t b[2];
                ldB(b, sWr + (q * 16 + j * 8 + r4) * XB + kb);
                mma_tf32(acc3[j], a, b);
            }
        }
        #pragma unroll
        for (int rh = 0; rh < 2; rh++) {
            int gn = base + m0 + rh * 8 + r4;
            if (gn < NN) {
                #pragma unroll
                for (int j = 0; j < 2; j++) {
                    int c0 = q * 16 + j * 8 + c2;
                    float2 o = make_float2(acc3[j][rh * 2] + sbr[c0],
                                           acc3[j][rh * 2 + 1] + sbr[c0 + 1]);
                    *(float2*)(out + (size_t)gn * 64 + c0) = o;
                }
            }
        }
    }
}

// ---------------------------------------------------------------------------
extern "C" void kernel_launch(void* const* d_in, const int* in_sizes, int n_in,
                              void* d_out, int out_size) {
    const float* src   = (const float*)d_in[0];
    const int*   eidx  = (const int*)d_in[1];
    const float* eattr = (const float*)d_in[2];
    const float* W1a = (const float*)d_in[5];
    const float* b1a = (const float*)d_in[6];
    const float* W1b = (const float*)d_in[7];
    const float* b1b = (const float*)d_in[8];
    const float* W2a = (const float*)d_in[9];
    const float* b2a = (const float*)d_in[10];
    const float* W2b = (const float*)d_in[11];
    const float* b2b = (const float*)d_in[12];
    const float* Wr  = (const float*)d_in[13];
    const float* br  = (const float*)d_in[14];
    float* out = (float*)d_out;

    cudaFuncSetAttribute(p_kernel,    cudaFuncAttributeMaxDynamicSharedMemorySize, SMEM_P);
    cudaFuncSetAttribute(edge_kernel, cudaFuncAttributeMaxDynamicSharedMemorySize, SMEM_EDGE);
    cudaFuncSetAttribute(node_kernel, cudaFuncAttributeMaxDynamicSharedMemorySize, SMEM_NODE);

    zero_kernel<<<(NN * 16 + 255) / 256, 256>>>();
    p_kernel<<<(NN + 63) / 64, 256, SMEM_P>>>(src, W1a, b1a);
    edge_kernel<<<296, 256, SMEM_EDGE>>>(eidx, eattr, W1a, W1b, b1b);
    node_kernel<<<148, 512, SMEM_NODE>>>(src, W2a, b2a, W2b, b2b, Wr, br, out);
}